// round 10
// baseline (speedup 1.0000x reference)
#include <cuda_runtime.h>
#include <math_constants.h>

// ---------------------------------------------------------------------------
// EstimatorQNN, 2 qubits, 2 layers — fused FLAT kernel (R10).
//
// Algebra: encoded state psi = (c0,s0)(x)(c1,s1); variational circuit = fixed
// 4x4 unitary U(weights); <Z0> = psi^T S psi, S = Re(U^H (Z(x)I) U).
// Double-angle collapse: result = 9 coefficients K over
// {1,cos(pi x0),sin(pi x0)} x {1,cos(pi x1),sin(pi x1)} -> 2 sincos + 8 FMA.
//
// Design from R3/R6/R9 evidence:
//  * FLAT launch, 4 samples/thread (2x LDG.128 + 1x STG.128): the shape with
//    the best measured streaming rate (3.58 TB/s read, 9.38 us).
//  * Fused per-block K prologue: threads 0-3 prefetch weights as 3x float4
//    (parallel, NOT 12 serial LDGs — that was R6's 3000-cycle barrier stall),
//    simulate the 4 basis columns; 16 threads reduce S; thread 0 folds K.
//  * Every thread issues its input loads BEFORE the prologue, so the ~600-cyc
//    barrier wait hides under the in-flight DRAM latency.
// ---------------------------------------------------------------------------

struct Cx { float re, im; };

__device__ __forceinline__ Cx cmul(Cx a, Cx b) {
    Cx r; r.re = a.re * b.re - a.im * b.im; r.im = a.re * b.im + a.im * b.re; return r;
}
__device__ __forceinline__ Cx cadd(Cx a, Cx b) { Cx r; r.re = a.re + b.re; r.im = a.im + b.im; return r; }

__device__ __forceinline__ void apply_gate(Cx s[4], Cx m00, Cx m01, Cx m10, Cx m11, int q) {
    if (q == 0) {
#pragma unroll
        for (int j = 0; j < 2; j++) {
            Cx a = s[j], b = s[j + 2];
            s[j]     = cadd(cmul(m00, a), cmul(m01, b));
            s[j + 2] = cadd(cmul(m10, a), cmul(m11, b));
        }
    } else {
#pragma unroll
        for (int j = 0; j < 4; j += 2) {
            Cx a = s[j], b = s[j + 1];
            s[j]     = cadd(cmul(m00, a), cmul(m01, b));
            s[j + 1] = cadd(cmul(m10, a), cmul(m11, b));
        }
    }
}

struct KScratch {
    Cx U[4][4];       // U[k][b]
    float S[4][4];
    float K[9];
};

// Block-level K derivation into sc->K. Only threads 0-3 touch wr (prefetched
// weights in registers); 16 threads reduce; thread 0 folds. 3 block barriers.
__device__ void block_build_K(const float wr[12], KScratch* sc) {
    int t = threadIdx.x;
    if (t < 4) {
        int b = t;
        Cx s[4];
#pragma unroll
        for (int k = 0; k < 4; k++) { s[k].re = (k == b) ? 1.0f : 0.0f; s[k].im = 0.0f; }
#pragma unroll
        for (int layer = 0; layer < 2; layer++) {
            int off = layer * 6;
#pragma unroll
            for (int q = 0; q < 2; q++) {
                float tx = wr[off + q * 3 + 0];
                float tz = wr[off + q * 3 + 1];
                float ty = wr[off + q * 3 + 2];
                float c, sn;
                c = __cosf(0.5f * tx); sn = __sinf(0.5f * tx);
                { Cx m00{c,0}, m01{0,-sn}, m10{0,-sn}, m11{c,0};
                  apply_gate(s, m00, m01, m10, m11, q); }
                c = __cosf(0.5f * tz); sn = __sinf(0.5f * tz);
                { Cx m00{c,-sn}, m01{0,0}, m10{0,0}, m11{c,sn};
                  apply_gate(s, m00, m01, m10, m11, q); }
                c = __cosf(0.5f * ty); sn = __sinf(0.5f * ty);
                { Cx m00{c,0}, m01{-sn,0}, m10{sn,0}, m11{c,0};
                  apply_gate(s, m00, m01, m10, m11, q); }
            }
            Cx tmp = s[2]; s[2] = s[3]; s[3] = tmp;  // CNOT(0->1): swap |10>,|11>
        }
#pragma unroll
        for (int k = 0; k < 4; k++) sc->U[k][b] = s[k];
    }
    __syncthreads();
    if (t < 16) {
        int i = t >> 2, j = t & 3;
        float acc = 0.0f;
#pragma unroll
        for (int k = 0; k < 4; k++) {
            float zk = (k < 2) ? 1.0f : -1.0f;
            acc += zk * (sc->U[k][i].re * sc->U[k][j].re + sc->U[k][i].im * sc->U[k][j].im);
        }
        sc->S[i][j] = acc;
    }
    __syncthreads();
    if (t == 0) {
        float c0 = sc->S[0][0], c1 = sc->S[1][1], c2 = sc->S[2][2], c3 = sc->S[3][3];
        float c4 = 2.0f * sc->S[0][1], c5 = 2.0f * sc->S[0][2], c6 = 2.0f * sc->S[0][3];
        float c7 = 2.0f * sc->S[1][2], c8 = 2.0f * sc->S[1][3], c9 = 2.0f * sc->S[2][3];
        sc->K[0] = 0.25f * (c0 + c1 + c2 + c3);   // 1
        sc->K[1] = 0.25f * (c0 - c1 + c2 - c3);   // C1
        sc->K[2] = 0.25f * (c4 + c9);             // S1
        sc->K[3] = 0.25f * (c0 + c1 - c2 - c3);   // C0
        sc->K[4] = 0.25f * (c0 - c1 - c2 + c3);   // C0*C1
        sc->K[5] = 0.25f * (c4 - c9);             // C0*S1
        sc->K[6] = 0.25f * (c5 + c8);             // S0
        sc->K[7] = 0.25f * (c5 - c8);             // S0*C1
        sc->K[8] = 0.25f * (c6 + c7);             // S0*S1
    }
    __syncthreads();
}

__device__ __forceinline__ float eval_one(float x0, float x1, const float k[9]) {
    float S0, C0, S1, C1;
    __sincosf(CUDART_PI_F * x0, &S0, &C0);
    __sincosf(CUDART_PI_F * x1, &S1, &C1);
    float t1 = fmaf(k[2], S1, fmaf(k[1], C1, k[0]));
    float t2 = fmaf(k[5], S1, fmaf(k[4], C1, k[3]));
    float t3 = fmaf(k[8], S1, fmaf(k[7], C1, k[6]));
    return fmaf(S0, t3, fmaf(C0, t2, t1));
}

// Flat fused kernel: one 4-sample tile per thread (2x float4 in, 1 float4 out).
__global__ void __launch_bounds__(256, 8) qnn_fused_flat_kernel(
    const float4* __restrict__ in, float4* __restrict__ out,
    const float4* __restrict__ w4, int n_quads) {
    __shared__ KScratch sc;
    int t = threadIdx.x;

    // Weight prefetch: only the 4 simulating threads load (one L2 line,
    // parallel float4s — no serial chain, minimal issue cost).
    float wr[12];
    if (t < 4) {
        float4 w0 = w4[0], w1 = w4[1], w2 = w4[2];
        wr[0] = w0.x; wr[1]  = w0.y; wr[2]  = w0.z; wr[3]  = w0.w;
        wr[4] = w1.x; wr[5]  = w1.y; wr[6]  = w1.z; wr[7]  = w1.w;
        wr[8] = w2.x; wr[9]  = w2.y; wr[10] = w2.z; wr[11] = w2.w;
    }

    // Issue the input loads BEFORE the prologue; barrier wait hides under them.
    int i = blockIdx.x * blockDim.x + t;
    bool valid = (i < n_quads);
    float4 a, b;
    if (valid) {
        a = in[2 * (size_t)i];
        b = in[2 * (size_t)i + 1];
    }

    block_build_K(wr, &sc);

    float k[9];
#pragma unroll
    for (int j = 0; j < 9; j++) k[j] = sc.K[j];

    if (!valid) return;

    float4 r;
    r.x = eval_one(a.x, a.y, k);
    r.y = eval_one(a.z, a.w, k);
    r.z = eval_one(b.x, b.y, k);
    r.w = eval_one(b.z, b.w, k);
    out[i] = r;
}

// Scalar tail for B % 4 != 0 (not hit for B = 4194304).
__global__ void qnn_tail_kernel(const float2* __restrict__ in,
                                float* __restrict__ out,
                                const float4* __restrict__ w4, int start, int B) {
    __shared__ KScratch sc;
    int t = threadIdx.x;
    float wr[12];
    if (t < 4) {
        float4 w0 = w4[0], w1 = w4[1], w2 = w4[2];
        wr[0] = w0.x; wr[1]  = w0.y; wr[2]  = w0.z; wr[3]  = w0.w;
        wr[4] = w1.x; wr[5]  = w1.y; wr[6]  = w1.z; wr[7]  = w1.w;
        wr[8] = w2.x; wr[9]  = w2.y; wr[10] = w2.z; wr[11] = w2.w;
    }
    block_build_K(wr, &sc);
    float k[9];
#pragma unroll
    for (int j = 0; j < 9; j++) k[j] = sc.K[j];
    int i = start + blockIdx.x * blockDim.x + t;
    if (i >= B) return;
    float2 x = in[i];
    out[i] = eval_one(x.x, x.y, k);
}

extern "C" void kernel_launch(void* const* d_in, const int* in_sizes, int n_in,
                              void* d_out, int out_size) {
    const float* inputs  = (const float*)d_in[0];   // [B,2]
    const float* weights = (const float*)d_in[1];   // [12]

    int B = in_sizes[0] / 2;            // 4194304
    int n_quads = B / 4;                // 1048576
    if (n_quads > 0) {
        int threads = 256;
        int blocks = (n_quads + threads - 1) / threads;   // 4096
        qnn_fused_flat_kernel<<<blocks, threads>>>((const float4*)inputs,
                                                   (float4*)d_out,
                                                   (const float4*)weights, n_quads);
    }
    int done = n_quads * 4;
    if (done < B) {
        int rem = B - done;
        qnn_tail_kernel<<<(rem + 127) / 128, 128>>>((const float2*)inputs,
                                                    (float*)d_out,
                                                    (const float4*)weights, done, B);
    }
}

// round 11
// speedup vs baseline: 1.2800x; 1.2800x over previous
#include <cuda_runtime.h>
#include <math_constants.h>

// ---------------------------------------------------------------------------
// EstimatorQNN, 2 qubits, 2 layers — persistent fused kernel, software-
// pipelined (R11).
//
// Algebra: encoded state psi = (c0,s0)(x)(c1,s1); variational circuit = fixed
// 4x4 unitary U(weights); <Z0> = psi^T S psi, S = Re(U^H (Z(x)I) U).
// Double-angle collapse: result = 9 coefficients K over
// {1,cos(pi x0),sin(pi x0)} x {1,cos(pi x1),sin(pi x1)} -> 2 sincos + 8 FMA.
//
// Structure (from R9/R10 evidence):
//  * persistent grid = 148*7 = 1036 blocks, launch_bounds(256,7) (<=36 regs):
//    ALL blocks resident in one wave -> K prologue paid once per block.
//  * K prologue with weights prefetched as 3x float4 (parallel, not serial).
//  * grid-stride loop SOFTWARE-PIPELINED: next iteration's 2x float4 loads
//    issue before the current eval, keeping loads in flight through the
//    dependent sincos/FMA chain (R9 was latency-bound: DRAM 35%, issue 42%).
// ---------------------------------------------------------------------------

struct Cx { float re, im; };

__device__ __forceinline__ Cx cmul(Cx a, Cx b) {
    Cx r; r.re = a.re * b.re - a.im * b.im; r.im = a.re * b.im + a.im * b.re; return r;
}
__device__ __forceinline__ Cx cadd(Cx a, Cx b) { Cx r; r.re = a.re + b.re; r.im = a.im + b.im; return r; }

__device__ __forceinline__ void apply_gate(Cx s[4], Cx m00, Cx m01, Cx m10, Cx m11, int q) {
    if (q == 0) {
#pragma unroll
        for (int j = 0; j < 2; j++) {
            Cx a = s[j], b = s[j + 2];
            s[j]     = cadd(cmul(m00, a), cmul(m01, b));
            s[j + 2] = cadd(cmul(m10, a), cmul(m11, b));
        }
    } else {
#pragma unroll
        for (int j = 0; j < 4; j += 2) {
            Cx a = s[j], b = s[j + 1];
            s[j]     = cadd(cmul(m00, a), cmul(m01, b));
            s[j + 1] = cadd(cmul(m10, a), cmul(m11, b));
        }
    }
}

struct KScratch {
    Cx U[4][4];       // U[k][b]
    float S[4][4];
    float K[9];
};

// Block-level K derivation into sc->K. Weights passed in registers (only
// threads 0-3 hold valid wr).
__device__ void block_build_K(const float wr[12], KScratch* sc) {
    int t = threadIdx.x;
    if (t < 4) {
        int b = t;
        Cx s[4];
#pragma unroll
        for (int k = 0; k < 4; k++) { s[k].re = (k == b) ? 1.0f : 0.0f; s[k].im = 0.0f; }
#pragma unroll
        for (int layer = 0; layer < 2; layer++) {
            int off = layer * 6;
#pragma unroll
            for (int q = 0; q < 2; q++) {
                float tx = wr[off + q * 3 + 0];
                float tz = wr[off + q * 3 + 1];
                float ty = wr[off + q * 3 + 2];
                float c, sn;
                c = __cosf(0.5f * tx); sn = __sinf(0.5f * tx);
                { Cx m00{c,0}, m01{0,-sn}, m10{0,-sn}, m11{c,0};
                  apply_gate(s, m00, m01, m10, m11, q); }
                c = __cosf(0.5f * tz); sn = __sinf(0.5f * tz);
                { Cx m00{c,-sn}, m01{0,0}, m10{0,0}, m11{c,sn};
                  apply_gate(s, m00, m01, m10, m11, q); }
                c = __cosf(0.5f * ty); sn = __sinf(0.5f * ty);
                { Cx m00{c,0}, m01{-sn,0}, m10{sn,0}, m11{c,0};
                  apply_gate(s, m00, m01, m10, m11, q); }
            }
            Cx tmp = s[2]; s[2] = s[3]; s[3] = tmp;  // CNOT(0->1): swap |10>,|11>
        }
#pragma unroll
        for (int k = 0; k < 4; k++) sc->U[k][b] = s[k];
    }
    __syncthreads();
    if (t < 16) {
        int i = t >> 2, j = t & 3;
        float acc = 0.0f;
#pragma unroll
        for (int k = 0; k < 4; k++) {
            float zk = (k < 2) ? 1.0f : -1.0f;
            acc += zk * (sc->U[k][i].re * sc->U[k][j].re + sc->U[k][i].im * sc->U[k][j].im);
        }
        sc->S[i][j] = acc;
    }
    __syncthreads();
    if (t == 0) {
        float c0 = sc->S[0][0], c1 = sc->S[1][1], c2 = sc->S[2][2], c3 = sc->S[3][3];
        float c4 = 2.0f * sc->S[0][1], c5 = 2.0f * sc->S[0][2], c6 = 2.0f * sc->S[0][3];
        float c7 = 2.0f * sc->S[1][2], c8 = 2.0f * sc->S[1][3], c9 = 2.0f * sc->S[2][3];
        sc->K[0] = 0.25f * (c0 + c1 + c2 + c3);   // 1
        sc->K[1] = 0.25f * (c0 - c1 + c2 - c3);   // C1
        sc->K[2] = 0.25f * (c4 + c9);             // S1
        sc->K[3] = 0.25f * (c0 + c1 - c2 - c3);   // C0
        sc->K[4] = 0.25f * (c0 - c1 - c2 + c3);   // C0*C1
        sc->K[5] = 0.25f * (c4 - c9);             // C0*S1
        sc->K[6] = 0.25f * (c5 + c8);             // S0
        sc->K[7] = 0.25f * (c5 - c8);             // S0*C1
        sc->K[8] = 0.25f * (c6 + c7);             // S0*S1
    }
    __syncthreads();
}

__device__ __forceinline__ float eval_one(float x0, float x1, const float k[9]) {
    float S0, C0, S1, C1;
    __sincosf(CUDART_PI_F * x0, &S0, &C0);
    __sincosf(CUDART_PI_F * x1, &S1, &C1);
    float t1 = fmaf(k[2], S1, fmaf(k[1], C1, k[0]));
    float t2 = fmaf(k[5], S1, fmaf(k[4], C1, k[3]));
    float t3 = fmaf(k[8], S1, fmaf(k[7], C1, k[6]));
    return fmaf(S0, t3, fmaf(C0, t2, t1));
}

// Persistent pipelined kernel. 4 samples/thread/iter (2x float4 in, 1 out);
// next iteration's loads issue before the current eval.
__global__ void __launch_bounds__(256, 7) qnn_persistent_kernel(
    const float4* __restrict__ in, float4* __restrict__ out,
    const float4* __restrict__ w4, int n_quads) {
    __shared__ KScratch sc;
    int t = threadIdx.x;

    // Weight prefetch: only the 4 simulating threads load (parallel float4s).
    float wr[12];
    if (t < 4) {
        float4 w0 = w4[0], w1 = w4[1], w2 = w4[2];
        wr[0] = w0.x; wr[1]  = w0.y; wr[2]  = w0.z; wr[3]  = w0.w;
        wr[4] = w1.x; wr[5]  = w1.y; wr[6]  = w1.z; wr[7]  = w1.w;
        wr[8] = w2.x; wr[9]  = w2.y; wr[10] = w2.z; wr[11] = w2.w;
    }

    // Issue first-iteration loads BEFORE the prologue (hides the barriers).
    int stride = gridDim.x * blockDim.x;
    int i = blockIdx.x * blockDim.x + t;
    float4 a, b;
    if (i < n_quads) {
        a = in[2 * (size_t)i];
        b = in[2 * (size_t)i + 1];
    }

    block_build_K(wr, &sc);

    float k[9];
#pragma unroll
    for (int j = 0; j < 9; j++) k[j] = sc.K[j];

    if (i >= n_quads) return;

    // Software-pipelined grid-stride loop.
    for (;;) {
        int inext = i + stride;
        bool have_next = (inext < n_quads);
        float4 an, bn;
        if (have_next) {                     // prefetch next tile
            an = in[2 * (size_t)inext];
            bn = in[2 * (size_t)inext + 1];
        }

        float4 r;
        r.x = eval_one(a.x, a.y, k);
        r.y = eval_one(a.z, a.w, k);
        r.z = eval_one(b.x, b.y, k);
        r.w = eval_one(b.z, b.w, k);
        out[i] = r;

        if (!have_next) break;
        a = an; b = bn; i = inext;
    }
}

// Scalar tail for B % 4 != 0 (not hit for B = 4194304).
__global__ void qnn_tail_kernel(const float2* __restrict__ in,
                                float* __restrict__ out,
                                const float4* __restrict__ w4, int start, int B) {
    __shared__ KScratch sc;
    int t = threadIdx.x;
    float wr[12];
    if (t < 4) {
        float4 w0 = w4[0], w1 = w4[1], w2 = w4[2];
        wr[0] = w0.x; wr[1]  = w0.y; wr[2]  = w0.z; wr[3]  = w0.w;
        wr[4] = w1.x; wr[5]  = w1.y; wr[6]  = w1.z; wr[7]  = w1.w;
        wr[8] = w2.x; wr[9]  = w2.y; wr[10] = w2.z; wr[11] = w2.w;
    }
    block_build_K(wr, &sc);
    float k[9];
#pragma unroll
    for (int j = 0; j < 9; j++) k[j] = sc.K[j];
    int i = start + blockIdx.x * blockDim.x + t;
    if (i >= B) return;
    float2 x = in[i];
    out[i] = eval_one(x.x, x.y, k);
}

extern "C" void kernel_launch(void* const* d_in, const int* in_sizes, int n_in,
                              void* d_out, int out_size) {
    const float* inputs  = (const float*)d_in[0];   // [B,2]
    const float* weights = (const float*)d_in[1];   // [12]

    int B = in_sizes[0] / 2;            // 4194304
    int n_quads = B / 4;                // 1048576
    if (n_quads > 0) {
        int threads = 256;
        int blocks = 148 * 7;                            // 1036: one full wave at 7/SM
        int max_needed = (n_quads + threads - 1) / threads;
        if (blocks > max_needed) blocks = max_needed;
        qnn_persistent_kernel<<<blocks, threads>>>((const float4*)inputs,
                                                   (float4*)d_out,
                                                   (const float4*)weights, n_quads);
    }
    int done = n_quads * 4;
    if (done < B) {
        int rem = B - done;
        qnn_tail_kernel<<<(rem + 127) / 128, 128>>>((const float2*)inputs,
                                                    (float*)d_out,
                                                    (const float4*)weights, done, B);
    }
}